// round 4
// baseline (speedup 1.0000x reference)
#include <cuda_runtime.h>

// StochasticPool2d: 2x2 stride-2 gumbel-max stochastic pooling.
// x:      [B=32, C=64, H=224, W=224] fp32
// gumbel: [B,C,112,112,4] fp32
// out:    [B,C,112,112] fp32
//
// HBM-roofline streaming kernel, persistent grid-stride form: one wave of
// 148 SMs x 8 CTAs x 256 threads; each thread loops ~42 pair-iterations.
// Per iteration: 4x LDG.128 + 1x STG.64, fully coalesced (grid-stride keeps
// warps contiguous). No wave transitions, loop lets ptxas pipeline loads
// across iterations.

static constexpr int Hc = 224;
static constexpr int Wc = 224;
static constexpr int NH = 112;
static constexpr int NW = 112;
static constexpr int N_OUT   = 32 * 64 * NH * NW;   // 25,690,112
static constexpr int N_PAIRS = N_OUT / 2;           // 12,845,056
static constexpr int PPR     = NW / 2;              // 56 pairs per output row

static constexpr int THREADS = 256;
static constexpr int CTAS    = 148 * 8;             // one full wave at occ=8

__device__ __forceinline__ float pick4(float v0, float v1, float v2, float v3,
                                       float g0, float g1, float g2, float g3)
{
    // score_k = (v_k > 0 ? log(v_k) : log(1)=0) + gumbel_k ; first-max argmax
    float s0 = (v0 > 0.0f ? __logf(v0) : 0.0f) + g0;
    float s1 = (v1 > 0.0f ? __logf(v1) : 0.0f) + g1;
    float s2 = (v2 > 0.0f ? __logf(v2) : 0.0f) + g2;
    float s3 = (v3 > 0.0f ? __logf(v3) : 0.0f) + g3;

    float best_s = s0;
    float best_v = v0;
    if (s1 > best_s) { best_s = s1; best_v = v1; }
    if (s2 > best_s) { best_s = s2; best_v = v2; }
    if (s3 > best_s) { best_s = s3; best_v = v3; }
    return best_v;
}

__global__ void __launch_bounds__(THREADS)
stochastic_pool2d_kernel(const float* __restrict__ x,
                         const float* __restrict__ gum,
                         float* __restrict__ out)
{
    const int stride = CTAS * THREADS;               // 303,104
    for (int t = blockIdx.x * THREADS + threadIdx.x; t < N_PAIRS; t += stride) {
        // t -> (bc, i, jp). jp covers output cols [2*jp, 2*jp+1].
        int jp = t % PPR;
        int r  = t / PPR;
        int i  = r % NH;
        int bc = r / NH;      // fused B*C index, < 2048

        // x: two input rows (2i, 2i+1), 4 consecutive floats, starting col 4*jp.
        const float* xrow = x + (size_t)bc * (Hc * Wc) + (2 * i) * Wc + 4 * jp;
        float4 x0 = *reinterpret_cast<const float4*>(xrow);        // row 2i
        float4 x1 = *reinterpret_cast<const float4*>(xrow + Wc);   // row 2i+1

        // gumbel: [.., i, j, 4] — 2 pixels = 8 contiguous floats, 32B aligned.
        const float* gp = gum + ((size_t)bc * (NH * NW) + i * NW + 2 * jp) * 4;
        float4 g0 = *reinterpret_cast<const float4*>(gp);
        float4 g1 = *reinterpret_cast<const float4*>(gp + 4);

        // Window flatten order k = di*2 + dj (row-major within 2x2).
        float2 o;
        o.x = pick4(x0.x, x0.y, x1.x, x1.y, g0.x, g0.y, g0.z, g0.w); // pixel 2*jp
        o.y = pick4(x0.z, x0.w, x1.z, x1.w, g1.x, g1.y, g1.z, g1.w); // pixel 2*jp+1

        float* op = out + (size_t)bc * (NH * NW) + i * NW + 2 * jp;
        *reinterpret_cast<float2*>(op) = o;
    }
}

extern "C" void kernel_launch(void* const* d_in, const int* in_sizes, int n_in,
                              void* d_out, int out_size)
{
    const float* x   = (const float*)d_in[0];
    const float* gum = (const float*)d_in[1];
    float* out = (float*)d_out;

    stochastic_pool2d_kernel<<<CTAS, THREADS>>>(x, gum, out);
}

// round 5
// speedup vs baseline: 1.0946x; 1.0946x over previous
#include <cuda_runtime.h>

// StochasticPool2d: 2x2 stride-2 gumbel-max stochastic pooling.
// x:      [B=32, C=64, H=224, W=224] fp32
// gumbel: [B,C,112,112,4] fp32
// out:    [B,C,112,112] fp32
//
// HBM-roofline one-shot streaming kernel (R1 shape: 2 output pixels/thread,
// 256-thread CTAs, ~80% occ). Index math minimized: with pair index t,
//   out  offset = 2*t               (pairs are contiguous)
//   gum  offset = 8*t               (4 floats per pixel, contiguous)
//   x    offset = 8*t - 4*(t % 56)  (only one mod on the whole path)
// Gumbel loads issue immediately; x loads right after the single mod.

static constexpr int Wc = 224;
static constexpr int NW = 112;
static constexpr int N_OUT   = 32 * 64 * 112 * NW;  // 25,690,112
static constexpr int N_PAIRS = N_OUT / 2;           // 12,845,056
static constexpr int PPR     = NW / 2;              // 56 pairs per output row

__device__ __forceinline__ float pick4(float v0, float v1, float v2, float v3,
                                       float g0, float g1, float g2, float g3)
{
    // score_k = (v_k > 0 ? log(v_k) : log(1)=0) + gumbel_k ; first-max argmax
    float s0 = (v0 > 0.0f ? __logf(v0) : 0.0f) + g0;
    float s1 = (v1 > 0.0f ? __logf(v1) : 0.0f) + g1;
    float s2 = (v2 > 0.0f ? __logf(v2) : 0.0f) + g2;
    float s3 = (v3 > 0.0f ? __logf(v3) : 0.0f) + g3;

    float best_s = s0;
    float best_v = v0;
    if (s1 > best_s) { best_s = s1; best_v = v1; }
    if (s2 > best_s) { best_s = s2; best_v = v2; }
    if (s3 > best_s) { best_s = s3; best_v = v3; }
    return best_v;
}

__global__ void __launch_bounds__(256)
stochastic_pool2d_kernel(const float* __restrict__ x,
                         const float* __restrict__ gum,
                         float* __restrict__ out)
{
    int t = blockIdx.x * blockDim.x + threadIdx.x;   // pair index, always < N_PAIRS

    // gumbel address is linear in t — loads issue immediately.
    const float* gp = gum + (size_t)t * 8;
    float4 g0 = *reinterpret_cast<const float4*>(gp);
    float4 g1 = *reinterpret_cast<const float4*>(gp + 4);

    // x: offset = 8t - 4*(t % 56); second window row is +Wc.
    int jp = t % PPR;
    const float* xrow = x + ((size_t)t * 8 - (size_t)(4 * jp));
    float4 x0 = *reinterpret_cast<const float4*>(xrow);        // row 2i
    float4 x1 = *reinterpret_cast<const float4*>(xrow + Wc);   // row 2i+1

    // Window flatten order k = di*2 + dj (row-major within 2x2).
    float2 o;
    o.x = pick4(x0.x, x0.y, x1.x, x1.y, g0.x, g0.y, g0.z, g0.w); // pixel 2t
    o.y = pick4(x0.z, x0.w, x1.z, x1.w, g1.x, g1.y, g1.z, g1.w); // pixel 2t+1

    *reinterpret_cast<float2*>(out + (size_t)t * 2) = o;
}

extern "C" void kernel_launch(void* const* d_in, const int* in_sizes, int n_in,
                              void* d_out, int out_size)
{
    const float* x   = (const float*)d_in[0];
    const float* gum = (const float*)d_in[1];
    float* out = (float*)d_out;

    const int threads = 256;
    const int blocks  = N_PAIRS / threads;   // 50,176 exactly
    stochastic_pool2d_kernel<<<blocks, threads>>>(x, gum, out);
}